// round 6
// baseline (speedup 1.0000x reference)
#include <cuda_runtime.h>
#include <cstdint>

// h_t = tanh(x_t @ W_ih^T + b_ih + b_hh + h_{t-1} @ W_hh^T); out = h_{T-1}
// B=4096, T=512, IN=15, HID=20.
//
// Warp-synchronous design (NO __syncthreads): 10 lanes per batch, 3 batches
// per warp (lanes 30,31 idle). Thread = (batch, hidden units 2t, 2t+1).
// Packed fma.rn.f32x2 along the k (reduction) dimension: operand pairs come
// directly from LDS.128, weights pre-packed in registers.
// x prefetched from GMEM at distance 3 via an explicit register FIFO
// (DRAM ~577cyc > ~3 steps at the ~180cyc/step target).

#define T_STEPS 512
#define BATCH   4096
#define N_IN    15
#define N_HID   20
#define GROUP   10                 // lanes per batch
#define BPW     3                  // batches per warp
#define WARPS_CTA 2
#define THREADS (WARPS_CTA * 32)   // 64
#define BPC     (WARPS_CTA * BPW)  // 6 batches per CTA
#define N_CTAS  ((BATCH + BPC - 1) / BPC)  // 683

typedef unsigned long long ull;

__device__ __forceinline__ ull pack2(float lo, float hi) {
    ull r; asm("mov.b64 %0, {%1, %2};" : "=l"(r) : "f"(lo), "f"(hi)); return r;
}
__device__ __forceinline__ ull fma2(ull a, ull b, ull c) {
    ull d; asm("fma.rn.f32x2 %0, %1, %2, %3;" : "=l"(d) : "l"(a), "l"(b), "l"(c)); return d;
}
__device__ __forceinline__ ull add2(ull a, ull b) {
    ull d; asm("add.rn.f32x2 %0, %1, %2;" : "=l"(d) : "l"(a), "l"(b)); return d;
}
__device__ __forceinline__ float hsum2(ull a) {
    float lo, hi; asm("mov.b64 {%0, %1}, %2;" : "=f"(lo), "=f"(hi) : "l"(a));
    return lo + hi;
}
__device__ __forceinline__ float fast_tanh(float z) {
    // tanh(z) = 1 - 2/(exp(2z)+1); ~1e-6 rel err, monotone, saturates correctly
    float e = __expf(2.0f * z);
    return 1.0f - __fdividef(2.0f, e + 1.0f);
}

__global__ __launch_bounds__(THREADS, 8)
void rnn_warp_kernel(const float* __restrict__ feature,
                     const float* __restrict__ W_ih,
                     const float* __restrict__ W_hh,
                     const float* __restrict__ b_ih,
                     const float* __restrict__ b_hh,
                     float* __restrict__ out)
{
    // double-buffered per-batch staging; rows 16-byte aligned for LDS.128
    __shared__ __align__(16) float xs[2][BPC][16];  // x_t (15 + pad0)
    __shared__ __align__(16) float hs[2][BPC][20];  // h_{t-1}

    const int tid  = threadIdx.x;
    const int wid  = tid >> 5;
    const int lane = tid & 31;
    const int g    = lane / GROUP;           // 0..2 batch slot, 3 = idle lanes
    const int tl   = lane % GROUP;           // 0..9 within batch
    const bool active = (g < BPW);
    const int lb   = active ? (wid * BPW + g) : 0;
    const int b    = blockIdx.x * BPC + lb;
    const bool valid = active && (b < BATCH);
    const bool v5   = valid && (tl < 5);     // lanes covering x elements 10..14

    const int j0 = 2 * tl, j1 = 2 * tl + 1;  // this thread's hidden units

    // ---- pre-pack weights as f32x2 k-pairs (loop-invariant registers) ----
    ull wx0[8], wx1[8], wh0[10], wh1[10];
#pragma unroll
    for (int p = 0; p < 8; p++) {
        float a1 = (2 * p + 1 < N_IN) ? W_ih[j0 * N_IN + 2 * p + 1] : 0.0f;
        float c1 = (2 * p + 1 < N_IN) ? W_ih[j1 * N_IN + 2 * p + 1] : 0.0f;
        wx0[p] = pack2(W_ih[j0 * N_IN + 2 * p], a1);
        wx1[p] = pack2(W_ih[j1 * N_IN + 2 * p], c1);
    }
#pragma unroll
    for (int p = 0; p < 10; p++) {
        wh0[p] = pack2(W_hh[j0 * N_HID + 2 * p], W_hh[j0 * N_HID + 2 * p + 1]);
        wh1[p] = pack2(W_hh[j1 * N_HID + 2 * p], W_hh[j1 * N_HID + 2 * p + 1]);
    }
    const ull bias2_0 = pack2(b_ih[j0] + b_hh[j0], 0.0f);
    const ull bias2_1 = pack2(b_ih[j1] + b_hh[j1], 0.0f);
    const ull zero2   = 0ull;

    // ---- prologue: h_{-1}=0, x_0 staged, x_1..x_3 in register FIFO ----
    const float* xrow = feature + (size_t)(valid ? b : 0) * T_STEPS * N_IN;
    if (active) {
        hs[0][lb][j0] = 0.0f;
        hs[0][lb][j1] = 0.0f;
        xs[0][lb][tl] = valid ? xrow[tl] : 0.0f;
        if (tl < 5) xs[0][lb][10 + tl] = valid ? xrow[10 + tl] : 0.0f;
        if (tl == 0) { xs[0][lb][15] = 0.0f; xs[1][lb][15] = 0.0f; }
    }
    // register FIFO: (fa1,fb1)=x_{t+1}, (fa2,fb2)=x_{t+2}, (fa3,fb3)=x_{t+3}
    float fa1 = valid ? xrow[1 * N_IN + tl] : 0.0f;
    float fb1 = v5    ? xrow[1 * N_IN + 10 + tl] : 0.0f;
    float fa2 = valid ? xrow[2 * N_IN + tl] : 0.0f;
    float fb2 = v5    ? xrow[2 * N_IN + 10 + tl] : 0.0f;
    float fa3 = valid ? xrow[3 * N_IN + tl] : 0.0f;
    float fb3 = v5    ? xrow[3 * N_IN + 10 + tl] : 0.0f;

    float h0 = 0.0f, h1 = 0.0f;

#pragma unroll 2
    for (int t = 0; t < T_STEPS; t++) {
        const int p = t & 1;
        __syncwarp();   // prev writes to buf p visible; prev reads of buf p^1 done

        // publish x_{t+1} from FIFO head
        if (active) {
            xs[p ^ 1][lb][tl] = fa1;
            if (tl < 5) xs[p ^ 1][lb][10 + tl] = fb1;
        }
        // shift FIFO, then prefetch x_{t+4} into the tail
        fa1 = fa2; fb1 = fb2;
        fa2 = fa3; fb2 = fb3;
        if (valid && (t + 4) < T_STEPS) {
            fa3 = xrow[(t + 4) * N_IN + tl];
            fb3 = (tl < 5) ? xrow[(t + 4) * N_IN + 10 + tl] : 0.0f;
        } else {
            fa3 = 0.0f; fb3 = 0.0f;
        }

        // gather x_t (4x LDS.128 -> 8 f32x2) and h_{t-1} (5x LDS.128 -> 10 f32x2)
        ull xp[8], hp[10];
        {
            const ulonglong2* xv = (const ulonglong2*)xs[p][lb];
            ulonglong2 v0 = xv[0], v1 = xv[1], v2 = xv[2], v3 = xv[3];
            xp[0] = v0.x; xp[1] = v0.y; xp[2] = v1.x; xp[3] = v1.y;
            xp[4] = v2.x; xp[5] = v2.y; xp[6] = v3.x; xp[7] = v3.y;
        }
        {
            const ulonglong2* hv = (const ulonglong2*)hs[p][lb];
            ulonglong2 v0 = hv[0], v1 = hv[1], v2 = hv[2], v3 = hv[3], v4 = hv[4];
            hp[0] = v0.x; hp[1] = v0.y; hp[2] = v1.x; hp[3] = v1.y;
            hp[4] = v2.x; hp[5] = v2.y; hp[6] = v3.x; hp[7] = v3.y;
            hp[8] = v4.x; hp[9] = v4.y;
        }

        // 18 fma2 per unit, 2 chains each (depth 9)
        ull a0 = bias2_0, b0 = zero2, a1 = bias2_1, b1 = zero2;
#pragma unroll
        for (int k = 0; k < 8; k++) {
            if (k & 1) { b0 = fma2(xp[k], wx0[k], b0); b1 = fma2(xp[k], wx1[k], b1); }
            else       { a0 = fma2(xp[k], wx0[k], a0); a1 = fma2(xp[k], wx1[k], a1); }
        }
#pragma unroll
        for (int k = 0; k < 10; k++) {
            if (k & 1) { b0 = fma2(hp[k], wh0[k], b0); b1 = fma2(hp[k], wh1[k], b1); }
            else       { a0 = fma2(hp[k], wh0[k], a0); a1 = fma2(hp[k], wh1[k], a1); }
        }
        const float z0 = hsum2(add2(a0, b0));
        const float z1 = hsum2(add2(a1, b1));

        h0 = fast_tanh(z0);
        h1 = fast_tanh(z1);

        if (active) {
            *(float2*)&hs[p ^ 1][lb][j0] = make_float2(h0, h1);
        }
    }

    if (valid) {
        out[b * N_HID + j0] = h0;
        out[b * N_HID + j1] = h1;
    }
}

extern "C" void kernel_launch(void* const* d_in, const int* in_sizes, int n_in,
                              void* d_out, int out_size)
{
    const float* feature = (const float*)d_in[0];
    const float* W_ih    = (const float*)d_in[1];
    const float* W_hh    = (const float*)d_in[2];
    const float* b_ih    = (const float*)d_in[3];
    const float* b_hh    = (const float*)d_in[4];
    float* out = (float*)d_out;

    rnn_warp_kernel<<<N_CTAS, THREADS>>>(feature, W_ih, W_hh, b_ih, b_hh, out);
}